// round 1
// baseline (speedup 1.0000x reference)
#include <cuda_runtime.h>
#include <math.h>

// Batched FFT: B=8192 rows, N=4096 points, complex fp32 (separate re/im arrays).
// out = [Y_re (B,N) ; Y_im (B,N)] concatenated.
//
// Algorithm: 4096 = 16*16*16 four-step decomposition.
//   n = n1*256 + n2, k = k2*16 + k1, n2 = p1*16 + p2, k2 = q2*16 + q1.
// Pass 1 (thread t = n2):  A[k1] = DFT16_{n1}( x[n1*256+t] ),  B = A * W4096^{t*k1}
// Exchange 1 (smem, pad 257)
// Pass 2 (thread = (k1,p2)): C[q1] = DFT16_{p1}( B[k1, p1*16+p2] ), D = C * W256^{p2*q1}
// Exchange 2 (smem)
// Pass 3 (thread = (k1,q1)): E[q2] = DFT16_{p2}( D ), Y[q2*256 + q1*16 + k1] = E[q2]
// Loads and stores are fully coalesced; 2 smem exchanges total.

#define NFFT 4096
#define TPB  256

__device__ __forceinline__ float2 cmul(float2 a, float2 b) {
    return make_float2(fmaf(a.x, b.x, -a.y * b.y),
                       fmaf(a.x, b.y,  a.y * b.x));
}

__device__ __forceinline__ void dft4(float2 a, float2 b, float2 c, float2 d,
                                     float2& o0, float2& o1, float2& o2, float2& o3) {
    // W4 = -i (forward DFT)
    float2 s0 = make_float2(a.x + c.x, a.y + c.y);
    float2 s1 = make_float2(a.x - c.x, a.y - c.y);
    float2 s2 = make_float2(b.x + d.x, b.y + d.y);
    float2 s3 = make_float2(b.x - d.x, b.y - d.y);
    o0 = make_float2(s0.x + s2.x, s0.y + s2.y);
    o2 = make_float2(s0.x - s2.x, s0.y - s2.y);
    o1 = make_float2(s1.x + s3.y, s1.y - s3.x);   // s1 - i*s3
    o3 = make_float2(s1.x - s3.y, s1.y + s3.x);   // s1 + i*s3
}

// 16-point forward DFT, natural order in -> natural order out.
// Radix-4 x radix-4:  A_l[p] = DFT4_m(v[4m+l]);  T = A_l[p]*W16^{lp};
//                     X[4s+p] = DFT4_l(T[l][p]).
__device__ __forceinline__ void fft16(float2 v[16]) {
    const float C1 = 0.92387953251128675613f;  // cos(pi/8)
    const float S1 = 0.38268343236508977173f;  // sin(pi/8)
    const float R  = 0.70710678118654752440f;  // sqrt(2)/2

    float2 a[4][4];
#pragma unroll
    for (int l = 0; l < 4; l++)
        dft4(v[l], v[l + 4], v[l + 8], v[l + 12],
             a[l][0], a[l][1], a[l][2], a[l][3]);

    // twiddle by W16^{l*p}, W16 = e^{-2*pi*i/16}
    a[1][1] = cmul(a[1][1], make_float2( C1, -S1));
    a[1][2] = cmul(a[1][2], make_float2(  R,  -R));
    a[1][3] = cmul(a[1][3], make_float2( S1, -C1));
    a[2][1] = cmul(a[2][1], make_float2(  R,  -R));
    { float2 x = a[2][2]; a[2][2] = make_float2(x.y, -x.x); }  // * (-i)
    a[2][3] = cmul(a[2][3], make_float2( -R,  -R));
    a[3][1] = cmul(a[3][1], make_float2( S1, -C1));
    a[3][2] = cmul(a[3][2], make_float2( -R,  -R));
    a[3][3] = cmul(a[3][3], make_float2(-C1,  S1));

#pragma unroll
    for (int p = 0; p < 4; p++)
        dft4(a[0][p], a[1][p], a[2][p], a[3][p],
             v[p], v[4 + p], v[8 + p], v[12 + p]);
}

__global__ void __launch_bounds__(TPB, 2)
fft4096_kernel(const float* __restrict__ xre,
               const float* __restrict__ xim,
               float* __restrict__ out,
               int batch) {
    __shared__ float2 sh[16 * 257];  // 4112 float2 = 32896 B (257-stride pad for exch 1)

    const int b = blockIdx.x;
    const int t = threadIdx.x;

    const float* xr = xre + (size_t)b * NFFT;
    const float* xi = xim + (size_t)b * NFFT;

    float2 v[16];
#pragma unroll
    for (int n1 = 0; n1 < 16; n1++)
        v[n1] = make_float2(xr[n1 * 256 + t], xi[n1 * 256 + t]);

    // ---- pass 1: DFT16 over n1, thread t = n2 ----
    fft16(v);

    // twiddle W4096^{t*k1} via recurrence from one sincos
    {
        float s, c;
        sincosf(-6.2831853071795864769f * (float)t / 4096.0f, &s, &c);
        float2 w  = make_float2(c, s);
        float2 wk = w;
#pragma unroll
        for (int k1 = 1; k1 < 16; k1++) {
            v[k1] = cmul(v[k1], wk);
            wk = cmul(wk, w);
        }
    }

    // ---- exchange 1: S1[k1*257 + n2] ----
#pragma unroll
    for (int k1 = 0; k1 < 16; k1++)
        sh[k1 * 257 + t] = v[k1];
    __syncthreads();

    {
        const int k1 = t & 15;
        const int p2 = t >> 4;
#pragma unroll
        for (int p1 = 0; p1 < 16; p1++)
            v[p1] = sh[k1 * 257 + p1 * 16 + p2];

        // ---- pass 2: DFT16 over p1 -> q1 ----
        fft16(v);

        // twiddle W256^{p2*q1}
        float s, c;
        sincosf(-6.2831853071795864769f * (float)p2 / 256.0f, &s, &c);
        float2 w  = make_float2(c, s);
        float2 wk = w;
#pragma unroll
        for (int q1 = 1; q1 < 16; q1++) {
            v[q1] = cmul(v[q1], wk);
            wk = cmul(wk, w);
        }
    }
    __syncthreads();

    // ---- exchange 2: S2[q1*256 + p2*16 + k1] = S2[q1*256 + t] ----
#pragma unroll
    for (int q1 = 0; q1 < 16; q1++)
        sh[q1 * 256 + t] = v[q1];
    __syncthreads();

    {
        const int k1 = t & 15;
        const int q1 = t >> 4;
#pragma unroll
        for (int p2 = 0; p2 < 16; p2++)
            v[p2] = sh[q1 * 256 + p2 * 16 + k1];
    }

    // ---- pass 3: DFT16 over p2 -> q2;  Y[q2*256 + t] = E[q2] ----
    fft16(v);

    float* outre = out + (size_t)b * NFFT;
    float* outim = out + (size_t)batch * NFFT + (size_t)b * NFFT;
#pragma unroll
    for (int q2 = 0; q2 < 16; q2++) {
        outre[q2 * 256 + t] = v[q2].x;
        outim[q2 * 256 + t] = v[q2].y;
    }
}

extern "C" void kernel_launch(void* const* d_in, const int* in_sizes, int n_in,
                              void* d_out, int out_size) {
    const float* xre = (const float*)d_in[0];
    const float* xim = (const float*)d_in[1];
    float* out = (float*)d_out;
    const int batch = in_sizes[0] / NFFT;

    fft4096_kernel<<<batch, TPB>>>(xre, xim, out, batch);
}